// round 16
// baseline (speedup 1.0000x reference)
#include <cuda_runtime.h>
#include <cuda.h>
#include <math.h>
#include <cstdint>

// ---------------- problem constants ----------------
#define NTOK   4096          // B*S
#define HDIM   4096
#define NEXP   8
#define TOPK   2
#define CAP    1536
#define NSEL   (NTOK*TOPK)
#define NCB    32            // column blocks (HDIM / BN)

#define DISPATCH_ELEMS  ((long long)NTOK*NEXP*CAP)
#define PROBS_OFF       (2LL*DISPATCH_ELEMS)
#define AUX_OFF         (PROBS_OFF + (long long)NTOK*NEXP)

// ---------------- device scratch ----------------
__device__ float g_partial[NCB][4][NTOK][NEXP];   // 16 MB per-warp partial logits
__device__ int   g_flat_idx[NSEL];
__device__ float g_flat_prob[NSEL];
__device__ int   g_pos[NSEL];
__device__ int   g_counts[NEXP];

// ---------------- helpers ----------------
__device__ __forceinline__ void cpasync16(uint32_t dst, const void* src) {
    asm volatile("cp.async.cg.shared.global [%0], [%1], 16;\n" :: "r"(dst), "l"(src));
}
#define CP_COMMIT() asm volatile("cp.async.commit_group;\n" ::: "memory")
#define CP_WAIT(n)  asm volatile("cp.async.wait_group %0;\n" :: "n"(n) : "memory")

__device__ __forceinline__ uint32_t smem_u32(const void* p) {
    uint32_t a;
    asm("{ .reg .u64 t; cvta.to.shared.u64 t, %1; cvt.u32.u64 %0, t; }" : "=r"(a) : "l"(p));
    return a;
}

// keep top 10 explicit mantissa bits (exactly fp16-representable in normal range)
__device__ __forceinline__ float hi10(float v) {
    return __uint_as_float(__float_as_uint(v) & 0xFFFFE000u);
}
// pack {low half = eve, high half = odd} as f16x2 (denormal-correct cvt)
__device__ __forceinline__ uint32_t pk(float eve, float odd) {
    uint32_t d;
    asm("cvt.rn.f16x2.f32 %0, %1, %2;" : "=r"(d) : "f"(odd), "f"(eve));
    return d;
}

// mma.sync m16n8k16 fp16 inputs, fp32 accum. Base ISA (sm_80+).
__device__ __forceinline__ void mma_f16(float c[4],
                                        uint32_t a0, uint32_t a1, uint32_t a2, uint32_t a3,
                                        uint32_t b0, uint32_t b1) {
    asm volatile(
        "mma.sync.aligned.m16n8k16.row.col.f32.f16.f16.f32 "
        "{%0,%1,%2,%3}, {%4,%5,%6,%7}, {%8,%9}, {%0,%1,%2,%3};"
        : "+f"(c[0]), "+f"(c[1]), "+f"(c[2]), "+f"(c[3])
        : "r"(a0), "r"(a1), "r"(a2), "r"(a3), "r"(b0), "r"(b1));
}

// ---------------- GEMM1: fp32 cp.async stage -> SMEM fp16 split (once) -> LDS+HMMA ----------------
#define BM 128
#define BN 128
#define BK 32
#define ASTRIDE 36                    // fp32 A stage stride (conflict-free for convert LDS.128)
#define BSTRIDE 132                   // fp32 B stage stride
#define ABYTES (BM * ASTRIDE * 4)     // 18432
#define BBYTES (BK * BSTRIDE * 4)     // 16896
#define STAGEBYTES (ABYTES + BBYTES)  // 35328
#define STAGEWORDS (STAGEBYTES / 4)
#define FW 20                         // fp16 tile stride in words (16 data + 4 pad)
#define TILEWORDS (128 * FW)          // 2560 words = 10240 B per tile
#define TILES_OFF (2 * STAGEWORDS)    // word offset of fp16 tiles
#define GSMEM (2 * STAGEBYTES + 4 * TILEWORDS * 4)   // 70656 + 40960 = 111616
#define ZPT 96                        // fused zero chunks per CTA

__global__ __launch_bounds__(256, 2) void gemm1_tc(
    const float* __restrict__ A, const float* __restrict__ B,
    const float* __restrict__ bias, const float* __restrict__ W2,
    float4* __restrict__ zout)
{
    extern __shared__ float smem[];
    const int tid = threadIdx.x;
    const int warp = tid >> 5, lane = tid & 31;
    const int wm = (warp & 1) * 64;       // warp m-offset
    const int wn = (warp >> 1) * 32;      // warp n-offset
    const int row0 = blockIdx.y * BM;
    const int col0 = blockIdx.x * BN;
    const int r = lane >> 2, cq = lane & 3;
    const int ctalin = blockIdx.y * 32 + blockIdx.x;   // 0..1023

    const uint32_t sb = smem_u32(smem);
    uint32_t* const Ah = (uint32_t*)smem + TILES_OFF;
    uint32_t* const Al = Ah + TILEWORDS;
    uint32_t* const Bh = Al + TILEWORDS;
    uint32_t* const Bl = Bh + TILEWORDS;

    if (ctalin == 0 && tid < NEXP) g_counts[tid] = 0;

    float acc[4][4][4];   // [mtile][ntile][frag]
    #pragma unroll
    for (int i = 0; i < 4; i++)
        #pragma unroll
        for (int j = 0; j < 4; j++)
            #pragma unroll
            for (int f = 0; f < 4; f++) acc[i][j][f] = 0.f;

    auto fill = [&](int buf, int kc) {
        const uint32_t st = sb + buf * STAGEBYTES;
        #pragma unroll
        for (int t = 0; t < 4; t++) {          // A: 1024 x 16B chunks
            int o = tid + t * 256;
            int rr = o >> 3, c16 = o & 7;
            cpasync16(st + (rr * ASTRIDE + c16 * 4) * 4,
                      A + (size_t)(row0 + rr) * HDIM + kc + c16 * 4);
        }
        #pragma unroll
        for (int t = 0; t < 4; t++) {          // B: 1024 x 16B chunks
            int o = tid + t * 256;
            int rr = o >> 5, c16 = o & 31;
            cpasync16(st + ABYTES + (rr * BSTRIDE + c16 * 4) * 4,
                      B + (size_t)(kc + rr) * HDIM + col0 + c16 * 4);
        }
    };

    // convert fp32 stage -> fp16 hi/lo tiles (split ONCE per CTA, not per warp)
    const int crow = tid & 127;        // row for A / n for B
    const int chalf = tid >> 7;        // which 16-k half
    auto convert = [&](int buf) {
        const float* As = smem + buf * STAGEWORDS;
        const float* Bs = As + ABYTES / 4;
        // ---- A: row-major, thread handles 16 consecutive k ----
        {
            const float* pa = As + crow * ASTRIDE + chalf * 16;
            uint32_t hw[8], lw[8];
            #pragma unroll
            for (int j = 0; j < 8; j++) {
                float v0 = pa[2 * j], v1 = pa[2 * j + 1];
                float h0 = hi10(v0), h1 = hi10(v1);
                hw[j] = pk(h0, h1);
                lw[j] = pk(v0 - h0, v1 - h1);
            }
            uint32_t* dh = Ah + crow * FW + chalf * 8;
            uint32_t* dl = Al + crow * FW + chalf * 8;
            *(uint4*)(dh) = make_uint4(hw[0], hw[1], hw[2], hw[3]);
            *(uint4*)(dh + 4) = make_uint4(hw[4], hw[5], hw[6], hw[7]);
            *(uint4*)(dl) = make_uint4(lw[0], lw[1], lw[2], lw[3]);
            *(uint4*)(dl + 4) = make_uint4(lw[4], lw[5], lw[6], lw[7]);
        }
        // ---- B: transpose k-major [k][n] -> n-major word tiles [n][kw] ----
        {
            const float* pb = Bs + (size_t)(chalf * 16) * BSTRIDE + crow;
            uint32_t hw[8], lw[8];
            #pragma unroll
            for (int j = 0; j < 8; j++) {
                float v0 = pb[(2 * j) * BSTRIDE], v1 = pb[(2 * j + 1) * BSTRIDE];
                float h0 = hi10(v0), h1 = hi10(v1);
                hw[j] = pk(h0, h1);
                lw[j] = pk(v0 - h0, v1 - h1);
            }
            uint32_t* dh = Bh + crow * FW + chalf * 8;
            uint32_t* dl = Bl + crow * FW + chalf * 8;
            *(uint4*)(dh) = make_uint4(hw[0], hw[1], hw[2], hw[3]);
            *(uint4*)(dh + 4) = make_uint4(hw[4], hw[5], hw[6], hw[7]);
            *(uint4*)(dl) = make_uint4(lw[0], lw[1], lw[2], lw[3]);
            *(uint4*)(dl + 4) = make_uint4(lw[4], lw[5], lw[6], lw[7]);
        }
    };

    const float4 z4 = make_float4(0.f, 0.f, 0.f, 0.f);
    const long long zbase = (long long)ctalin * (ZPT * 256) + tid;

    // mainloop over the fp16 tiles: pure LDS.32 -> HMMA
    auto chunk_mma = [&](int c) {
        if (c < ZPT) zout[zbase + (long long)c * 256] = z4;

        #pragma unroll
        for (int kk = 0; kk < 2; kk++) {
            const int kwb = kk * 8;
            uint32_t bhi[4][2], blo[4][2];
            #pragma unroll
            for (int nt = 0; nt < 4; nt++) {
                const int base = (wn + nt * 8 + r) * FW + kwb + cq;
                bhi[nt][0] = Bh[base]; bhi[nt][1] = Bh[base + 4];
                blo[nt][0] = Bl[base]; blo[nt][1] = Bl[base + 4];
            }
            #pragma unroll
            for (int mt = 0; mt < 4; mt++) {
                const int base = (wm + mt * 16 + r) * FW + kwb + cq;
                uint32_t ah0 = Ah[base];
                uint32_t ah1 = Ah[base + 8 * FW];
                uint32_t ah2 = Ah[base + 4];
                uint32_t ah3 = Ah[base + 8 * FW + 4];
                uint32_t al0 = Al[base];
                uint32_t al1 = Al[base + 8 * FW];
                uint32_t al2 = Al[base + 4];
                uint32_t al3 = Al[base + 8 * FW + 4];

                #pragma unroll
                for (int nt = 0; nt < 4; nt++)
                    mma_f16(acc[mt][nt], ah0, ah1, ah2, ah3, bhi[nt][0], bhi[nt][1]);
                #pragma unroll
                for (int nt = 0; nt < 4; nt++)
                    mma_f16(acc[mt][nt], ah0, ah1, ah2, ah3, blo[nt][0], blo[nt][1]);
                #pragma unroll
                for (int nt = 0; nt < 4; nt++)
                    mma_f16(acc[mt][nt], al0, al1, al2, al3, bhi[nt][0], bhi[nt][1]);
            }
        }
    };

    // ---- pipeline: 2 fp32 stages + 1 fp16 buffer ----
    fill(0, 0);  CP_COMMIT();
    fill(1, BK); CP_COMMIT();

    const int NCHUNK = HDIM / BK;   // 128
    for (int c = 0; c < NCHUNK; ++c) {
        if (c == NCHUNK - 1) { CP_WAIT(0); } else { CP_WAIT(1); }
        __syncthreads();               // all fills of chunk c visible; prior mainloop done
        convert(c & 1);
        __syncthreads();               // fp16 tiles ready; fp32 stage c&1 free
        if (c + 2 < NCHUNK) { fill(c & 1, (c + 2) * BK); CP_COMMIT(); }
        chunk_mma(c);
    }

    // ---- epilogue A: h = relu(acc + bias) in registers ----
    #pragma unroll
    for (int nt = 0; nt < 4; nt++) {
        int col = col0 + wn + nt * 8 + 2 * cq;
        float bx = __ldg(bias + col), by = __ldg(bias + col + 1);
        #pragma unroll
        for (int mt = 0; mt < 4; mt++) {
            acc[mt][nt][0] = fmaxf(acc[mt][nt][0] + bx, 0.f);
            acc[mt][nt][1] = fmaxf(acc[mt][nt][1] + by, 0.f);
            acc[mt][nt][2] = fmaxf(acc[mt][nt][2] + bx, 0.f);
            acc[mt][nt][3] = fmaxf(acc[mt][nt][3] + by, 0.f);
        }
    }

    // ---- epilogue B: logits partial via MMA (acc frags ARE the A fragments) ----
    {
        uint32_t wbh[2][2], wbl[2][2];
        #pragma unroll
        for (int kk = 0; kk < 2; kk++) {
            const float* w2p = W2 + (size_t)(col0 + wn + kk * 16) * NEXP + r;
            float q0 = __ldg(w2p + (2 * cq) * NEXP);
            float q1 = __ldg(w2p + (2 * cq + 1) * NEXP);
            float q2 = __ldg(w2p + (2 * cq + 8) * NEXP);
            float q3 = __ldg(w2p + (2 * cq + 9) * NEXP);
            float h;
            h = hi10(q0); float m0 = q0 - h; float g0 = h;
            h = hi10(q1); float m1 = q1 - h; float g1 = h;
            h = hi10(q2); float m2 = q2 - h; float g2 = h;
            h = hi10(q3); float m3 = q3 - h; float g3 = h;
            wbh[kk][0] = pk(g0, g1); wbl[kk][0] = pk(m0, m1);
            wbh[kk][1] = pk(g2, g3); wbl[kk][1] = pk(m2, m3);
        }

        float accL[4][4];
        #pragma unroll
        for (int mt = 0; mt < 4; mt++)
            #pragma unroll
            for (int f = 0; f < 4; f++) accL[mt][f] = 0.f;

        #pragma unroll
        for (int mt = 0; mt < 4; mt++) {
            #pragma unroll
            for (int kk = 0; kk < 2; kk++) {
                const float* f0 = acc[mt][2 * kk];
                const float* f1 = acc[mt][2 * kk + 1];
                float h;
                h = hi10(f0[0]); float l00 = f0[0] - h; float h00 = h;
                h = hi10(f0[1]); float l01 = f0[1] - h; float h01 = h;
                h = hi10(f0[2]); float l02 = f0[2] - h; float h02 = h;
                h = hi10(f0[3]); float l03 = f0[3] - h; float h03 = h;
                h = hi10(f1[0]); float l10 = f1[0] - h; float h10 = h;
                h = hi10(f1[1]); float l11 = f1[1] - h; float h11 = h;
                h = hi10(f1[2]); float l12 = f1[2] - h; float h12 = h;
                h = hi10(f1[3]); float l13 = f1[3] - h; float h13 = h;
                uint32_t ah0 = pk(h00, h01), al0 = pk(l00, l01);
                uint32_t ah1 = pk(h02, h03), al1 = pk(l02, l03);
                uint32_t ah2 = pk(h10, h11), al2 = pk(l10, l11);
                uint32_t ah3 = pk(h12, h13), al3 = pk(l12, l13);

                mma_f16(accL[mt], ah0, ah1, ah2, ah3, wbh[kk][0], wbh[kk][1]);
                mma_f16(accL[mt], ah0, ah1, ah2, ah3, wbl[kk][0], wbl[kk][1]);
                mma_f16(accL[mt], al0, al1, al2, al3, wbh[kk][0], wbh[kk][1]);
            }
        }

        // D-frag: c0=(row r, e=2cq) c1=(r, 2cq+1) c2=(r+8, 2cq) c3=(r+8, 2cq+1)
        const int ks = warp >> 1;
        #pragma unroll
        for (int mt = 0; mt < 4; mt++) {
            int row = row0 + wm + mt * 16 + r;
            float2 v0 = make_float2(accL[mt][0], accL[mt][1]);
            float2 v1 = make_float2(accL[mt][2], accL[mt][3]);
            *(float2*)(&g_partial[blockIdx.x][ks][row][2 * cq]) = v0;
            *(float2*)(&g_partial[blockIdx.x][ks][row + 8][2 * cq]) = v1;
        }
    }
}

// ---------------- combine partials + softmax + top-2 ----------------
__global__ void combine_topk(const float* __restrict__ b2, float* __restrict__ probs_out)
{
    int t = blockIdx.x * blockDim.x + threadIdx.x;
    if (t >= NTOK) return;

    float l[NEXP];
    #pragma unroll
    for (int e = 0; e < NEXP; e++) l[e] = b2[e];
    #pragma unroll 1
    for (int cb = 0; cb < NCB; cb++) {
        #pragma unroll
        for (int ks = 0; ks < 4; ks++) {
            const float* p = &g_partial[cb][ks][t][0];
            float4 a = *(const float4*)(p);
            float4 b = *(const float4*)(p + 4);
            l[0] += a.x; l[1] += a.y; l[2] += a.z; l[3] += a.w;
            l[4] += b.x; l[5] += b.y; l[6] += b.z; l[7] += b.w;
        }
    }

    float m = -1e30f;
    #pragma unroll
    for (int e = 0; e < NEXP; e++) m = fmaxf(m, l[e]);
    float s = 0.f;
    #pragma unroll
    for (int e = 0; e < NEXP; e++) { l[e] = expf(l[e] - m); s += l[e]; }
    float inv = 1.f / s;
    float p[NEXP];
    #pragma unroll
    for (int e = 0; e < NEXP; e++) { p[e] = l[e] * inv; probs_out[t * NEXP + e] = p[e]; }

    int i1 = 0; float p1 = p[0];
    #pragma unroll
    for (int e = 1; e < NEXP; e++) if (p[e] > p1) { p1 = p[e]; i1 = e; }
    int i2 = -1; float p2 = -1.f;
    #pragma unroll
    for (int e = 0; e < NEXP; e++) if (e != i1 && p[e] > p2) { p2 = p[e]; i2 = e; }

    float norm = 1.f / (p1 + p2 + 1e-8f);
    g_flat_idx[2 * t + 0] = i1;
    g_flat_idx[2 * t + 1] = i2;
    g_flat_prob[2 * t + 0] = p1 * norm;
    g_flat_prob[2 * t + 1] = p2 * norm;
    atomicAdd(&g_counts[i1], 1);
    atomicAdd(&g_counts[i2], 1);
}

// ---------------- exclusive per-expert position scan ----------------
__device__ __forceinline__ uint4 add4(uint4 a, uint4 b) {
    return make_uint4(a.x + b.x, a.y + b.y, a.z + b.z, a.w + b.w);
}
__device__ __forceinline__ uint4 sub4(uint4 a, uint4 b) {
    return make_uint4(a.x - b.x, a.y - b.y, a.z - b.z, a.w - b.w);
}
__global__ __launch_bounds__(1024) void scan_kernel()
{
    const int tid = threadIdx.x;
    const int lane = tid & 31, wid = tid >> 5;

    int e[8];
    uint4 pre[8];
    uint4 run = make_uint4(0, 0, 0, 0);
    #pragma unroll
    for (int i = 0; i < 8; i++) {
        e[i] = g_flat_idx[tid * 8 + i];
        pre[i] = run;
        unsigned word = (unsigned)e[i] >> 1;
        unsigned add = 1u << ((e[i] & 1) * 16);
        if (word == 0) run.x += add;
        else if (word == 1) run.y += add;
        else if (word == 2) run.z += add;
        else run.w += add;
    }
    const uint4 own = run;

    uint4 incl = own;
    #pragma unroll
    for (int off = 1; off < 32; off <<= 1) {
        unsigned vx = __shfl_up_sync(0xffffffffu, incl.x, off);
        unsigned vy = __shfl_up_sync(0xffffffffu, incl.y, off);
        unsigned vz = __shfl_up_sync(0xffffffffu, incl.z, off);
        unsigned vw = __shfl_up_sync(0xffffffffu, incl.w, off);
        if (lane >= off) { incl.x += vx; incl.y += vy; incl.z += vz; incl.w += vw; }
    }

    __shared__ uint4 wtot[32];
    if (lane == 31) wtot[wid] = incl;
    __syncthreads();
    if (wid == 0) {
        uint4 v = wtot[lane];
        uint4 inc2 = v;
        #pragma unroll
        for (int off = 1; off < 32; off <<= 1) {
            unsigned vx = __shfl_up_sync(0xffffffffu, inc2.x, off);
            unsigned vy = __shfl_up_sync(0xffffffffu, inc2.y, off);
            unsigned vz = __shfl_up_sync(0xffffffffu, inc2.z, off);
            unsigned vw = __shfl_up_sync(0xffffffffu, inc2.w, off);
            if (lane >= off) { inc2.x += vx; inc2.y += vy; inc2.z += vz; inc2.w += vw; }
        }
        wtot[lane] = sub4(inc2, v);
    }
    __syncthreads();

    const uint4 base = add4(wtot[wid], sub4(incl, own));
    #pragma unroll
    for (int i = 0; i < 8; i++) {
        uint4 tot = add4(base, pre[i]);
        unsigned word = (unsigned)e[i] >> 1;
        unsigned w = (word == 0) ? tot.x : (word == 1) ? tot.y : (word == 2) ? tot.z : tot.w;
        g_pos[tid * 8 + i] = (int)((w >> ((e[i] & 1) * 16)) & 0xFFFFu);
    }
}

// ---------------- scatter ----------------
__global__ void scatter_kernel(float* __restrict__ dispatch, float* __restrict__ combine)
{
    int n = blockIdx.x * blockDim.x + threadIdx.x;
    if (n >= NSEL) return;
    int p = g_pos[n];
    if (p < CAP) {
        int tok = n >> 1;
        int e = g_flat_idx[n];
        size_t off = ((size_t)tok * NEXP + e) * CAP + p;
        dispatch[off] = 1.0f;
        combine[off] = g_flat_prob[n];
    }
}

// ---------------- aux loss ----------------
__global__ void aux_kernel(const float* __restrict__ probs, float* __restrict__ aux_out)
{
    __shared__ float sh[256];
    const int tid = threadIdx.x;
    float local[NEXP];
    #pragma unroll
    for (int e = 0; e < NEXP; e++) local[e] = 0.f;
    for (int t = tid; t < NTOK; t += 256) {
        #pragma unroll
        for (int e = 0; e < NEXP; e++) local[e] += probs[t * NEXP + e];
    }
    float aux = 0.f;
    for (int e = 0; e < NEXP; e++) {
        sh[tid] = local[e];
        __syncthreads();
        for (int s = 128; s > 0; s >>= 1) {
            if (tid < s) sh[tid] += sh[tid + s];
            __syncthreads();
        }
        if (tid == 0)
            aux += (sh[0] / (float)NTOK) * ((float)g_counts[e] / (float)NSEL) * (float)NEXP;
        __syncthreads();
    }
    if (tid == 0) *aux_out = aux;
}

// ---------------- launch ----------------
extern "C" void kernel_launch(void* const* d_in, const int* in_sizes, int n_in,
                              void* d_out, int out_size)
{
    const float* x  = (const float*)d_in[0];
    const float* W1 = (const float*)d_in[1];
    const float* b1 = (const float*)d_in[2];
    const float* W2 = (const float*)d_in[3];
    const float* b2 = (const float*)d_in[4];

    float* out      = (float*)d_out;
    float* dispatch = out;
    float* combine  = out + DISPATCH_ELEMS;
    float* probs    = out + PROBS_OFF;
    float* aux      = out + AUX_OFF;

    static bool attr_set = false;
    if (!attr_set) {
        cudaFuncSetAttribute(gemm1_tc, cudaFuncAttributeMaxDynamicSharedMemorySize, GSMEM);
        attr_set = true;
    }

    // 1) GEMM1 (split-once SMEM convert, LDS+HMMA mainloop) + MMA logit partials + zeroing
    gemm1_tc<<<dim3(HDIM / BN, NTOK / BM), 256, GSMEM>>>(x, W1, b1, W2, (float4*)out);

    // 2) combine partials + softmax + top-2 (deterministic fixed-order sum)
    combine_topk<<<NTOK / 256, 256>>>(b2, probs);

    // 3) capacity position scan
    scan_kernel<<<1, 1024>>>();

    // 4) scatter
    scatter_kernel<<<NSEL / 256, 256>>>(dispatch, combine);

    // 5) aux loss
    aux_kernel<<<1, 256>>>(probs, aux);
}

// round 17
// speedup vs baseline: 1.0406x; 1.0406x over previous
#include <cuda_runtime.h>
#include <cuda.h>
#include <math.h>
#include <cstdint>

// ---------------- problem constants ----------------
#define NTOK   4096          // B*S
#define HDIM   4096
#define NEXP   8
#define TOPK   2
#define CAP    1536
#define NSEL   (NTOK*TOPK)
#define NCB    32            // column blocks (HDIM / BN)

#define DISPATCH_ELEMS  ((long long)NTOK*NEXP*CAP)
#define PROBS_OFF       (2LL*DISPATCH_ELEMS)
#define AUX_OFF         (PROBS_OFF + (long long)NTOK*NEXP)

// ---------------- device scratch ----------------
__device__ float g_partial[NCB][4][NTOK][NEXP];   // 16 MB per-warp partial logits
__device__ int   g_flat_idx[NSEL];
__device__ float g_flat_prob[NSEL];
__device__ int   g_counts[NEXP];

// ---------------- helpers ----------------
__device__ __forceinline__ void cpasync16(uint32_t dst, const void* src) {
    asm volatile("cp.async.cg.shared.global [%0], [%1], 16;\n" :: "r"(dst), "l"(src));
}
#define CP_COMMIT() asm volatile("cp.async.commit_group;\n" ::: "memory")
#define CP_WAIT(n)  asm volatile("cp.async.wait_group %0;\n" :: "n"(n) : "memory")

__device__ __forceinline__ uint32_t smem_u32(const void* p) {
    uint32_t a;
    asm("{ .reg .u64 t; cvta.to.shared.u64 t, %1; cvt.u32.u64 %0, t; }" : "=r"(a) : "l"(p));
    return a;
}

// keep top 10 explicit mantissa bits (exactly fp16-representable in normal range)
__device__ __forceinline__ float hi10(float v) {
    return __uint_as_float(__float_as_uint(v) & 0xFFFFE000u);
}
// pack {low half = eve, high half = odd} as f16x2 (denormal-correct cvt)
__device__ __forceinline__ uint32_t pk(float eve, float odd) {
    uint32_t d;
    asm("cvt.rn.f16x2.f32 %0, %1, %2;" : "=r"(d) : "f"(odd), "f"(eve));
    return d;
}

// mma.sync m16n8k16 fp16 inputs, fp32 accum. Base ISA (sm_80+).
__device__ __forceinline__ void mma_f16(float c[4],
                                        uint32_t a0, uint32_t a1, uint32_t a2, uint32_t a3,
                                        uint32_t b0, uint32_t b1) {
    asm volatile(
        "mma.sync.aligned.m16n8k16.row.col.f32.f16.f16.f32 "
        "{%0,%1,%2,%3}, {%4,%5,%6,%7}, {%8,%9}, {%0,%1,%2,%3};"
        : "+f"(c[0]), "+f"(c[1]), "+f"(c[2]), "+f"(c[3])
        : "r"(a0), "r"(a1), "r"(a2), "r"(a3), "r"(b0), "r"(b1));
}

// ---------------- GEMM1 (3-stage pipeline, ONE barrier per chunk) — round-15 best ----------------
#define BM 128
#define BN 128
#define BK 32
#define ASTRIDE 40     // %32==8 -> conflict-free LDS.64 k-pairs
#define BSTRIDE 132    // %32==4 -> conflict-free LDS.32
#define ABYTES (BM * ASTRIDE * 4)     // 20480
#define BBYTES (BK * BSTRIDE * 4)     // 16896
#define STAGEBYTES (ABYTES + BBYTES)  // 37376
#define NSTAGE 3
#define GSMEM (NSTAGE * STAGEBYTES)   // 112128
#define ZPT 96                        // fused zero chunks per CTA

__global__ __launch_bounds__(256, 2) void gemm1_tc(
    const float* __restrict__ A, const float* __restrict__ B,
    const float* __restrict__ bias, const float* __restrict__ W2,
    float4* __restrict__ zout)
{
    extern __shared__ float smem[];
    const int tid = threadIdx.x;
    const int warp = tid >> 5, lane = tid & 31;
    const int wm = (warp & 1) * 64;       // warp m-offset
    const int wn = (warp >> 1) * 32;      // warp n-offset
    const int row0 = blockIdx.y * BM;
    const int col0 = blockIdx.x * BN;
    const int r = lane >> 2, cq = lane & 3;
    const int ctalin = blockIdx.y * 32 + blockIdx.x;   // 0..1023

    const uint32_t sb = smem_u32(smem);

    if (ctalin == 0 && tid < NEXP) g_counts[tid] = 0;

    float acc[4][4][4];   // [mtile][ntile][frag]
    #pragma unroll
    for (int i = 0; i < 4; i++)
        #pragma unroll
        for (int j = 0; j < 4; j++)
            #pragma unroll
            for (int f = 0; f < 4; f++) acc[i][j][f] = 0.f;

    auto fill = [&](int buf, int kc) {
        const uint32_t st = sb + buf * STAGEBYTES;
        #pragma unroll
        for (int t = 0; t < 4; t++) {          // A: 1024 x 16B chunks
            int o = tid + t * 256;
            int rr = o >> 3, c16 = o & 7;
            cpasync16(st + (rr * ASTRIDE + c16 * 4) * 4,
                      A + (size_t)(row0 + rr) * HDIM + kc + c16 * 4);
        }
        #pragma unroll
        for (int t = 0; t < 4; t++) {          // B: 1024 x 16B chunks
            int o = tid + t * 256;
            int rr = o >> 5, c16 = o & 31;
            cpasync16(st + ABYTES + (rr * BSTRIDE + c16 * 4) * 4,
                      B + (size_t)(kc + rr) * HDIM + col0 + c16 * 4);
        }
    };

    const float4 z4 = make_float4(0.f, 0.f, 0.f, 0.f);
    const long long zbase = (long long)ctalin * (ZPT * 256) + tid;

    // mainloop body over one chunk's stage
    auto chunk_mma = [&](int stage, int c) {
        if (c < ZPT) zout[zbase + (long long)c * 256] = z4;

        const float* As = smem + (stage * STAGEBYTES) / 4;
        const float* Bs = As + ABYTES / 4;

        #pragma unroll
        for (int kk = 0; kk < 2; kk++) {       // two k16 steps
            const int kof = kk * 16;

            uint32_t bhi[4][2], blo[4][2];
            #pragma unroll
            for (int nt = 0; nt < 4; nt++) {
                const float* pb = Bs + (size_t)(kof + 2 * cq) * BSTRIDE + wn + nt * 8 + r;
                float q0 = pb[0];
                float q1 = pb[BSTRIDE];
                float q2 = pb[8 * BSTRIDE];
                float q3 = pb[9 * BSTRIDE];
                float h;
                h = hi10(q0); float m0 = q0 - h; float g0 = h;
                h = hi10(q1); float m1 = q1 - h; float g1 = h;
                h = hi10(q2); float m2 = q2 - h; float g2 = h;
                h = hi10(q3); float m3 = q3 - h; float g3 = h;
                bhi[nt][0] = pk(g0, g1); blo[nt][0] = pk(m0, m1);
                bhi[nt][1] = pk(g2, g3); blo[nt][1] = pk(m2, m3);
            }
            #pragma unroll
            for (int mt = 0; mt < 4; mt++) {
                const float* pa = As + (size_t)(wm + mt * 16 + r) * ASTRIDE + kof + 2 * cq;
                float2 p0 = *(const float2*)(pa);
                float2 p1 = *(const float2*)(pa + 8 * ASTRIDE);
                float2 p2 = *(const float2*)(pa + 8);
                float2 p3 = *(const float2*)(pa + 8 * ASTRIDE + 8);
                float h;
                h = hi10(p0.x); float l0x = p0.x - h; float h0x = h;
                h = hi10(p0.y); float l0y = p0.y - h; float h0y = h;
                h = hi10(p1.x); float l1x = p1.x - h; float h1x = h;
                h = hi10(p1.y); float l1y = p1.y - h; float h1y = h;
                h = hi10(p2.x); float l2x = p2.x - h; float h2x = h;
                h = hi10(p2.y); float l2y = p2.y - h; float h2y = h;
                h = hi10(p3.x); float l3x = p3.x - h; float h3x = h;
                h = hi10(p3.y); float l3y = p3.y - h; float h3y = h;
                uint32_t ah0 = pk(h0x, h0y), al0 = pk(l0x, l0y);
                uint32_t ah1 = pk(h1x, h1y), al1 = pk(l1x, l1y);
                uint32_t ah2 = pk(h2x, h2y), al2 = pk(l2x, l2y);
                uint32_t ah3 = pk(h3x, h3y), al3 = pk(l3x, l3y);

                #pragma unroll
                for (int nt = 0; nt < 4; nt++)
                    mma_f16(acc[mt][nt], ah0, ah1, ah2, ah3, bhi[nt][0], bhi[nt][1]);
                #pragma unroll
                for (int nt = 0; nt < 4; nt++)
                    mma_f16(acc[mt][nt], ah0, ah1, ah2, ah3, blo[nt][0], blo[nt][1]);
                #pragma unroll
                for (int nt = 0; nt < 4; nt++)
                    mma_f16(acc[mt][nt], al0, al1, al2, al3, bhi[nt][0], bhi[nt][1]);
            }
        }
    };

    // ---- 3-stage pipeline: ONE __syncthreads per chunk ----
    fill(0, 0);            CP_COMMIT();
    fill(1, BK);           CP_COMMIT();

    const int NCHUNK = HDIM / BK;   // 128
    for (int c = 0; c < NCHUNK - 1; ++c) {
        CP_WAIT(1);
        __syncthreads();
        if (c + 2 < NCHUNK) { fill((c + 2) % NSTAGE, (c + 2) * BK); CP_COMMIT(); }
        chunk_mma(c % NSTAGE, c);
    }
    CP_WAIT(0);
    __syncthreads();
    chunk_mma((NCHUNK - 1) % NSTAGE, NCHUNK - 1);

    // ---- epilogue A: h = relu(acc + bias) in registers ----
    #pragma unroll
    for (int nt = 0; nt < 4; nt++) {
        int col = col0 + wn + nt * 8 + 2 * cq;
        float bx = __ldg(bias + col), by = __ldg(bias + col + 1);
        #pragma unroll
        for (int mt = 0; mt < 4; mt++) {
            acc[mt][nt][0] = fmaxf(acc[mt][nt][0] + bx, 0.f);
            acc[mt][nt][1] = fmaxf(acc[mt][nt][1] + by, 0.f);
            acc[mt][nt][2] = fmaxf(acc[mt][nt][2] + bx, 0.f);
            acc[mt][nt][3] = fmaxf(acc[mt][nt][3] + by, 0.f);
        }
    }

    // ---- epilogue B: logits partial via MMA (acc frags ARE the A fragments) ----
    {
        uint32_t wbh[2][2], wbl[2][2];
        #pragma unroll
        for (int kk = 0; kk < 2; kk++) {
            const float* w2p = W2 + (size_t)(col0 + wn + kk * 16) * NEXP + r;
            float q0 = __ldg(w2p + (2 * cq) * NEXP);
            float q1 = __ldg(w2p + (2 * cq + 1) * NEXP);
            float q2 = __ldg(w2p + (2 * cq + 8) * NEXP);
            float q3 = __ldg(w2p + (2 * cq + 9) * NEXP);
            float h;
            h = hi10(q0); float m0 = q0 - h; float g0 = h;
            h = hi10(q1); float m1 = q1 - h; float g1 = h;
            h = hi10(q2); float m2 = q2 - h; float g2 = h;
            h = hi10(q3); float m3 = q3 - h; float g3 = h;
            wbh[kk][0] = pk(g0, g1); wbl[kk][0] = pk(m0, m1);
            wbh[kk][1] = pk(g2, g3); wbl[kk][1] = pk(m2, m3);
        }

        float accL[4][4];
        #pragma unroll
        for (int mt = 0; mt < 4; mt++)
            #pragma unroll
            for (int f = 0; f < 4; f++) accL[mt][f] = 0.f;

        #pragma unroll
        for (int mt = 0; mt < 4; mt++) {
            #pragma unroll
            for (int kk = 0; kk < 2; kk++) {
                const float* f0 = acc[mt][2 * kk];
                const float* f1 = acc[mt][2 * kk + 1];
                float h;
                h = hi10(f0[0]); float l00 = f0[0] - h; float h00 = h;
                h = hi10(f0[1]); float l01 = f0[1] - h; float h01 = h;
                h = hi10(f0[2]); float l02 = f0[2] - h; float h02 = h;
                h = hi10(f0[3]); float l03 = f0[3] - h; float h03 = h;
                h = hi10(f1[0]); float l10 = f1[0] - h; float h10 = h;
                h = hi10(f1[1]); float l11 = f1[1] - h; float h11 = h;
                h = hi10(f1[2]); float l12 = f1[2] - h; float h12 = h;
                h = hi10(f1[3]); float l13 = f1[3] - h; float h13 = h;
                uint32_t ah0 = pk(h00, h01), al0 = pk(l00, l01);
                uint32_t ah1 = pk(h02, h03), al1 = pk(l02, l03);
                uint32_t ah2 = pk(h10, h11), al2 = pk(l10, l11);
                uint32_t ah3 = pk(h12, h13), al3 = pk(l12, l13);

                mma_f16(accL[mt], ah0, ah1, ah2, ah3, wbh[kk][0], wbh[kk][1]);
                mma_f16(accL[mt], ah0, ah1, ah2, ah3, wbl[kk][0], wbl[kk][1]);
                mma_f16(accL[mt], al0, al1, al2, al3, wbh[kk][0], wbh[kk][1]);
            }
        }

        const int ks = warp >> 1;
        #pragma unroll
        for (int mt = 0; mt < 4; mt++) {
            int row = row0 + wm + mt * 16 + r;
            float2 v0 = make_float2(accL[mt][0], accL[mt][1]);
            float2 v1 = make_float2(accL[mt][2], accL[mt][3]);
            *(float2*)(&g_partial[blockIdx.x][ks][row][2 * cq]) = v0;
            *(float2*)(&g_partial[blockIdx.x][ks][row + 8][2 * cq]) = v1;
        }
    }
}

// ---------------- combine partials + softmax + top-2 ----------------
__global__ void combine_topk(const float* __restrict__ b2, float* __restrict__ probs_out)
{
    int t = blockIdx.x * blockDim.x + threadIdx.x;
    if (t >= NTOK) return;

    float l[NEXP];
    #pragma unroll
    for (int e = 0; e < NEXP; e++) l[e] = b2[e];
    #pragma unroll 1
    for (int cb = 0; cb < NCB; cb++) {
        #pragma unroll
        for (int ks = 0; ks < 4; ks++) {
            const float* p = &g_partial[cb][ks][t][0];
            float4 a = *(const float4*)(p);
            float4 b = *(const float4*)(p + 4);
            l[0] += a.x; l[1] += a.y; l[2] += a.z; l[3] += a.w;
            l[4] += b.x; l[5] += b.y; l[6] += b.z; l[7] += b.w;
        }
    }

    float m = -1e30f;
    #pragma unroll
    for (int e = 0; e < NEXP; e++) m = fmaxf(m, l[e]);
    float s = 0.f;
    #pragma unroll
    for (int e = 0; e < NEXP; e++) { l[e] = expf(l[e] - m); s += l[e]; }
    float inv = 1.f / s;
    float p[NEXP];
    #pragma unroll
    for (int e = 0; e < NEXP; e++) { p[e] = l[e] * inv; probs_out[t * NEXP + e] = p[e]; }

    int i1 = 0; float p1 = p[0];
    #pragma unroll
    for (int e = 1; e < NEXP; e++) if (p[e] > p1) { p1 = p[e]; i1 = e; }
    int i2 = -1; float p2 = -1.f;
    #pragma unroll
    for (int e = 0; e < NEXP; e++) if (e != i1 && p[e] > p2) { p2 = p[e]; i2 = e; }

    float norm = 1.f / (p1 + p2 + 1e-8f);
    g_flat_idx[2 * t + 0] = i1;
    g_flat_idx[2 * t + 1] = i2;
    g_flat_prob[2 * t + 0] = p1 * norm;
    g_flat_prob[2 * t + 1] = p2 * norm;
    atomicAdd(&g_counts[i1], 1);
    atomicAdd(&g_counts[i2], 1);
}

// ---------------- finalize: scan + scatter + aux in ONE single-block kernel ----------------
__device__ __forceinline__ uint4 add4(uint4 a, uint4 b) {
    return make_uint4(a.x + b.x, a.y + b.y, a.z + b.z, a.w + b.w);
}
__device__ __forceinline__ uint4 sub4(uint4 a, uint4 b) {
    return make_uint4(a.x - b.x, a.y - b.y, a.z - b.z, a.w - b.w);
}
__global__ __launch_bounds__(1024) void finalize_kernel(
    const float* __restrict__ probs, float* __restrict__ dispatch,
    float* __restrict__ combine, float* __restrict__ aux_out)
{
    const int tid = threadIdx.x;
    const int lane = tid & 31, wid = tid >> 5;

    // ---- exclusive per-expert position scan (8 picks per thread, registers) ----
    int e[8];
    uint4 pre[8];
    uint4 run = make_uint4(0, 0, 0, 0);
    #pragma unroll
    for (int i = 0; i < 8; i++) {
        e[i] = g_flat_idx[tid * 8 + i];
        pre[i] = run;
        unsigned word = (unsigned)e[i] >> 1;
        unsigned add = 1u << ((e[i] & 1) * 16);
        if (word == 0) run.x += add;
        else if (word == 1) run.y += add;
        else if (word == 2) run.z += add;
        else run.w += add;
    }
    const uint4 own = run;

    uint4 incl = own;
    #pragma unroll
    for (int off = 1; off < 32; off <<= 1) {
        unsigned vx = __shfl_up_sync(0xffffffffu, incl.x, off);
        unsigned vy = __shfl_up_sync(0xffffffffu, incl.y, off);
        unsigned vz = __shfl_up_sync(0xffffffffu, incl.z, off);
        unsigned vw = __shfl_up_sync(0xffffffffu, incl.w, off);
        if (lane >= off) { incl.x += vx; incl.y += vy; incl.z += vz; incl.w += vw; }
    }

    __shared__ uint4 wtot[32];
    if (lane == 31) wtot[wid] = incl;
    __syncthreads();
    if (wid == 0) {
        uint4 v = wtot[lane];
        uint4 inc2 = v;
        #pragma unroll
        for (int off = 1; off < 32; off <<= 1) {
            unsigned vx = __shfl_up_sync(0xffffffffu, inc2.x, off);
            unsigned vy = __shfl_up_sync(0xffffffffu, inc2.y, off);
            unsigned vz = __shfl_up_sync(0xffffffffu, inc2.z, off);
            unsigned vw = __shfl_up_sync(0xffffffffu, inc2.w, off);
            if (lane >= off) { inc2.x += vx; inc2.y += vy; inc2.z += vz; inc2.w += vw; }
        }
        wtot[lane] = sub4(inc2, v);
    }
    __syncthreads();

    const uint4 base = add4(wtot[wid], sub4(incl, own));

    // ---- scatter directly from registers (no g_pos round-trip) ----
    #pragma unroll
    for (int i = 0; i < 8; i++) {
        uint4 tot = add4(base, pre[i]);
        unsigned word = (unsigned)e[i] >> 1;
        unsigned w = (word == 0) ? tot.x : (word == 1) ? tot.y : (word == 2) ? tot.z : tot.w;
        int p = (int)((w >> ((e[i] & 1) * 16)) & 0xFFFFu);
        if (p < CAP) {
            int n = tid * 8 + i;
            int tok = n >> 1;
            size_t off = ((size_t)tok * NEXP + e[i]) * CAP + p;
            dispatch[off] = 1.0f;
            combine[off] = g_flat_prob[n];
        }
    }

    // ---- aux loss (fixed-order tree, deterministic) ----
    __shared__ float sh[1024];
    float local[NEXP];
    #pragma unroll
    for (int ee = 0; ee < NEXP; ee++) local[ee] = 0.f;
    for (int t = tid; t < NTOK; t += 1024) {
        #pragma unroll
        for (int ee = 0; ee < NEXP; ee++) local[ee] += probs[t * NEXP + ee];
    }
    float aux = 0.f;
    for (int ee = 0; ee < NEXP; ee++) {
        __syncthreads();
        sh[tid] = local[ee];
        __syncthreads();
        for (int s = 512; s > 0; s >>= 1) {
            if (tid < s) sh[tid] += sh[tid + s];
            __syncthreads();
        }
        if (tid == 0)
            aux += (sh[0] / (float)NTOK) * ((float)g_counts[ee] / (float)NSEL) * (float)NEXP;
    }
    if (tid == 0) *aux_out = aux;
}

// ---------------- launch ----------------
extern "C" void kernel_launch(void* const* d_in, const int* in_sizes, int n_in,
                              void* d_out, int out_size)
{
    const float* x  = (const float*)d_in[0];
    const float* W1 = (const float*)d_in[1];
    const float* b1 = (const float*)d_in[2];
    const float* W2 = (const float*)d_in[3];
    const float* b2 = (const float*)d_in[4];

    float* out      = (float*)d_out;
    float* dispatch = out;
    float* combine  = out + DISPATCH_ELEMS;
    float* probs    = out + PROBS_OFF;
    float* aux      = out + AUX_OFF;

    static bool attr_set = false;
    if (!attr_set) {
        cudaFuncSetAttribute(gemm1_tc, cudaFuncAttributeMaxDynamicSharedMemorySize, GSMEM);
        attr_set = true;
    }

    // 1) GEMM1 (3-stage, 1 barrier/chunk) + MMA logit partials + fused zeroing
    gemm1_tc<<<dim3(HDIM / BN, NTOK / BM), 256, GSMEM>>>(x, W1, b1, W2, (float4*)out);

    // 2) combine partials + softmax + top-2
    combine_topk<<<NTOK / 256, 256>>>(b2, probs);

    // 3) scan + scatter + aux fused (single block, deterministic)
    finalize_kernel<<<1, 1024>>>(probs, dispatch, combine, aux);
}